// round 1
// baseline (speedup 1.0000x reference)
#include <cuda_runtime.h>
#include <math.h>

#define D_MODEL 768
#define D_CONV  4
#define D_INNER 1536
#define BATCH   2
#define SEQ     8192

#define LCHUNK  256
#define WARM    256

// Scratch: static device globals (allocation-free rule)
__device__ float g_xz[(size_t)BATCH * SEQ * (2 * D_INNER)];  // 201 MB
__device__ float g_y [(size_t)BATCH * SEQ * D_INNER];        // 100 MB

// ---------------------------------------------------------------------------
// Classic register-tiled fp32 GEMM with bias: C[M,N] = A[M,K] @ B[K,N] + bias
// BM=BN=128, BK=8, TM=TN=8, 256 threads. Requires M%128==0, N%128==0, K%8==0.
// ---------------------------------------------------------------------------
template<int BM, int BN, int BK, int TM, int TN>
__global__ __launch_bounds__(256)
void sgemm_bias(int M, int N, int K,
                const float* __restrict__ A,
                const float* __restrict__ B,
                const float* __restrict__ bias,
                float* __restrict__ C)
{
    __shared__ float As[BK][BM];
    __shared__ float Bs[BK][BN];

    const int tid = threadIdx.x;
    const int tx  = tid & 15;   // 0..15 -> col tile
    const int ty  = tid >> 4;   // 0..15 -> row tile

    const int rowBase = blockIdx.y * BM;
    const int colBase = blockIdx.x * BN;

    // A-tile load mapping: 128 rows x 8 cols, one float4 per thread
    const int aRow = tid & 127;
    const int aCol = (tid >> 7) << 2;    // 0 or 4
    // B-tile load mapping: 8 rows x 128 cols, one float4 per thread
    const int bRow = tid >> 5;           // 0..7
    const int bCol = (tid & 31) << 2;    // 0..124

    float acc[TM][TN];
    #pragma unroll
    for (int i = 0; i < TM; i++)
        #pragma unroll
        for (int j = 0; j < TN; j++)
            acc[i][j] = 0.0f;

    const float* Aptr = A + (size_t)(rowBase + aRow) * K + aCol;
    const float* Bptr = B + (size_t)bRow * N + colBase + bCol;

    for (int k0 = 0; k0 < K; k0 += BK) {
        float4 a4 = *reinterpret_cast<const float4*>(Aptr + k0);
        As[aCol + 0][aRow] = a4.x;
        As[aCol + 1][aRow] = a4.y;
        As[aCol + 2][aRow] = a4.z;
        As[aCol + 3][aRow] = a4.w;

        float4 b4 = *reinterpret_cast<const float4*>(Bptr + (size_t)k0 * N);
        *reinterpret_cast<float4*>(&Bs[bRow][bCol]) = b4;

        __syncthreads();

        #pragma unroll
        for (int kk = 0; kk < BK; kk++) {
            float ar[TM], br[TN];
            *reinterpret_cast<float4*>(&ar[0]) = *reinterpret_cast<const float4*>(&As[kk][ty * TM]);
            *reinterpret_cast<float4*>(&ar[4]) = *reinterpret_cast<const float4*>(&As[kk][ty * TM + 4]);
            *reinterpret_cast<float4*>(&br[0]) = *reinterpret_cast<const float4*>(&Bs[kk][tx * TN]);
            *reinterpret_cast<float4*>(&br[4]) = *reinterpret_cast<const float4*>(&Bs[kk][tx * TN + 4]);
            #pragma unroll
            for (int i = 0; i < TM; i++)
                #pragma unroll
                for (int j = 0; j < TN; j++)
                    acc[i][j] = fmaf(ar[i], br[j], acc[i][j]);
        }
        __syncthreads();
    }

    // Epilogue: add bias, vectorized stores
    float4 bi0 = *reinterpret_cast<const float4*>(&bias[colBase + tx * TN]);
    float4 bi1 = *reinterpret_cast<const float4*>(&bias[colBase + tx * TN + 4]);
    #pragma unroll
    for (int i = 0; i < TM; i++) {
        size_t crow = (size_t)(rowBase + ty * TM + i) * N + colBase + tx * TN;
        float4 o0, o1;
        o0.x = acc[i][0] + bi0.x; o0.y = acc[i][1] + bi0.y;
        o0.z = acc[i][2] + bi0.z; o0.w = acc[i][3] + bi0.w;
        o1.x = acc[i][4] + bi1.x; o1.y = acc[i][5] + bi1.y;
        o1.z = acc[i][6] + bi1.z; o1.w = acc[i][7] + bi1.w;
        *reinterpret_cast<float4*>(&C[crow])     = o0;
        *reinterpret_cast<float4*>(&C[crow + 4]) = o1;
    }
}

// ---------------------------------------------------------------------------
// Fused: causal depthwise conv(4) + silu + EMA scan + D skip + silu(z) gate.
// EMA kernel decays as 0.9^k: 0.9^256 ~= 2e-12, so each LCHUNK of T is
// computed independently with a WARM-step warm-up (chunk 0 exact from h=0).
// One thread per channel; warp covers 32 consecutive channels -> coalesced.
// xz layout: [B, T, 2*D_INNER]  (x_inner = [:, :, :1536], z = [:, :, 1536:])
// ---------------------------------------------------------------------------
__global__ __launch_bounds__(128)
void conv_scan_kernel(const float* __restrict__ xz,
                      const float* __restrict__ cw,
                      const float* __restrict__ cb,
                      const float* __restrict__ Dp,
                      float* __restrict__ y)
{
    const int c  = blockIdx.x * 128 + threadIdx.x;   // channel 0..1535
    const int t0 = blockIdx.y * LCHUNK;
    const int b  = blockIdx.z;
    const int ts = (t0 >= WARM) ? (t0 - WARM) : 0;

    const float w0 = cw[c * D_CONV + 0];
    const float w1 = cw[c * D_CONV + 1];
    const float w2 = cw[c * D_CONV + 2];
    const float w3 = cw[c * D_CONV + 3];
    const float cbias = cb[c];
    const float dpar  = Dp[c];

    const float AL  = 0.9f;
    const float OMA = 1.0f - AL;

    const float* base = xz + (size_t)b * SEQ * (2 * D_INNER);

    // Preload 3 history samples for the conv window (zeros for t<0)
    float x0 = 0.f, x1 = 0.f, x2 = 0.f;
    #pragma unroll
    for (int dt = 3; dt >= 1; --dt) {
        int t = ts - dt;
        float v = (t >= 0) ? base[(size_t)t * (2 * D_INNER) + c] : 0.f;
        x0 = x1; x1 = x2; x2 = v;
    }

    float h = 0.f;
    const int tend = t0 + LCHUNK;

    #pragma unroll 4
    for (int t = ts; t < tend; ++t) {
        float xt = base[(size_t)t * (2 * D_INNER) + c];
        float conv = fmaf(w3, xt, fmaf(w2, x2, fmaf(w1, x1, fmaf(w0, x0, cbias))));
        x0 = x1; x1 = x2; x2 = xt;
        float xc = conv / (1.0f + __expf(-conv));   // silu
        h = fmaf(AL, h, OMA * xc);
        if (t >= t0) {
            float zv = base[(size_t)t * (2 * D_INNER) + D_INNER + c];
            float sz = zv / (1.0f + __expf(-zv));
            y[((size_t)b * SEQ + t) * D_INNER + c] = fmaf(xc, dpar, h) * sz;
        }
    }
}

// ---------------------------------------------------------------------------
extern "C" void kernel_launch(void* const* d_in, const int* in_sizes, int n_in,
                              void* d_out, int out_size)
{
    const float* x      = (const float*)d_in[0];
    const float* in_w   = (const float*)d_in[1];
    const float* in_b   = (const float*)d_in[2];
    const float* conv_w = (const float*)d_in[3];
    const float* conv_b = (const float*)d_in[4];
    // d_in[5..8] (xp_w, xp_b, dt_w, dt_b) are dead code in the reference
    const float* Dp     = (const float*)d_in[9];
    const float* out_w  = (const float*)d_in[10];
    const float* out_b  = (const float*)d_in[11];
    float* out = (float*)d_out;

    float *xz, *yb;
    cudaGetSymbolAddress((void**)&xz, g_xz);
    cudaGetSymbolAddress((void**)&yb, g_y);

    const int M = BATCH * SEQ;  // 16384

    // GEMM1: xz = x @ in_w + in_b   [16384,768] x [768,3072]
    dim3 g1((2 * D_INNER) / 128, M / 128);
    sgemm_bias<128, 128, 8, 8, 8><<<g1, 256>>>(M, 2 * D_INNER, D_MODEL, x, in_w, in_b, xz);

    // Fused conv/silu/scan/gate -> y   [16384,1536]
    dim3 g2(D_INNER / 128, SEQ / LCHUNK, BATCH);
    conv_scan_kernel<<<g2, 128>>>(xz, conv_w, conv_b, Dp, yb);

    // GEMM2: out = y @ out_w + out_b   [16384,1536] x [1536,768]
    dim3 g3(D_MODEL / 128, M / 128);
    sgemm_bias<128, 128, 8, 8, 8><<<g3, 256>>>(M, D_MODEL, D_INNER, yb, out_w, out_b, out);
}

// round 3
// speedup vs baseline: 2.2172x; 2.2172x over previous
#include <cuda_runtime.h>
#include <cuda_bf16.h>
#include <cstdint>

#define D_MODEL 768
#define D_CONV  4
#define D_INNER 1536
#define BATCH   2
#define SEQ     8192
#define MTOT    (BATCH*SEQ)     // 16384

#define K1  D_MODEL             // 768
#define N1  (2*D_INNER)         // 3072
#define K1S (3*K1)              // 2304
#define K2  D_INNER             // 1536
#define N2  D_MODEL             // 768
#define K2S (3*K2)              // 4608

#define BM 128
#define BN 128
#define BK 64                   // bf16 per chunk: 128 B/row = SW128 atom
#define STAGES 3
#define NTHREADS 256

#define LCHUNK 256
#define WARM   256

// ---------------- scratch (static device globals; no allocation) -----------
__device__ __nv_bfloat16 g_a1[(size_t)MTOT * K1S];   // x split      (75 MB)
__device__ __nv_bfloat16 g_b1[(size_t)N1  * K1S];    // in_w^T split (14 MB)
__device__ float         g_xz[(size_t)MTOT * N1];    // GEMM1 out   (201 MB)
__device__ __nv_bfloat16 g_a2[(size_t)MTOT * K2S];   // y split     (151 MB)
__device__ __nv_bfloat16 g_b2[(size_t)N2  * K2S];    // out_w^T split (7 MB)

// ---------------- PTX helpers ----------------------------------------------
__device__ __forceinline__ uint32_t smem_u32(const void* p) {
    uint32_t a;
    asm("{ .reg .u64 t; cvta.to.shared.u64 t, %1; cvt.u32.u64 %0, t; }" : "=r"(a) : "l"(p));
    return a;
}
#define SWZ128(off) ((off) ^ (((off) >> 3) & 0x70))

#define CP_ASYNC16(s, g) \
    asm volatile("cp.async.cg.shared.global [%0], [%1], 16;\n" :: "r"(s), "l"(g) : "memory")
#define CP_COMMIT() asm volatile("cp.async.commit_group;\n" ::: "memory")
#define CP_WAIT(n)  asm volatile("cp.async.wait_group %0;\n" :: "n"(n) : "memory")

#define LDMATRIX_X4(r0, r1, r2, r3, addr) \
    asm volatile("ldmatrix.sync.aligned.m8n8.x4.shared.b16 {%0,%1,%2,%3}, [%4];" \
        : "=r"(r0), "=r"(r1), "=r"(r2), "=r"(r3) : "r"(addr))

#define MMA_BF16(d0,d1,d2,d3, a0,a1,a2,a3, b0,b1) \
    asm volatile("mma.sync.aligned.m16n8k16.row.col.f32.bf16.bf16.f32 " \
        "{%0,%1,%2,%3}, {%4,%5,%6,%7}, {%8,%9}, {%0,%1,%2,%3};" \
        : "+f"(d0), "+f"(d1), "+f"(d2), "+f"(d3) \
        : "r"(a0), "r"(a1), "r"(a2), "r"(a3), "r"(b0), "r"(b1))

// SMEM per stage: A 128x64 bf16 (16 KB) + B 128x64 bf16 (16 KB)
#define A_BYTES (BM * 128)
#define B_BYTES (BN * 128)
#define STAGE_BYTES (A_BYTES + B_BYTES)     // 32768
#define SMEM_TOTAL (STAGES * STAGE_BYTES)   // 98304

// ---------------------------------------------------------------------------
// mma.sync bf16 GEMM: C[M,N] fp32 = A[M,K] @ Bt[N,K]^T + bias
// A, Bt K-major bf16. 128x128x64 tile, 3-stage cp.async, 8 warps (4M x 2N).
// ---------------------------------------------------------------------------
__global__ __launch_bounds__(NTHREADS, 2)
void gemm_bf16_mma(const __nv_bfloat16* __restrict__ A,
                   const __nv_bfloat16* __restrict__ Bt,
                   const float* __restrict__ bias,
                   float* __restrict__ C,
                   int M, int N, int K)
{
    extern __shared__ char smem[];
    const uint32_t sbase = smem_u32(smem);
    const int tid  = threadIdx.x;
    const int wid  = tid >> 5;
    const int lane = tid & 31;
    const int warpM = wid & 3;          // 0..3  -> 32-row slice
    const int warpN = wid >> 2;         // 0..1  -> 64-col slice

    const int mBase = blockIdx.y * BM;
    const int nBase = blockIdx.x * BN;

    const __nv_bfloat16* Abase = A  + (size_t)mBase * K;
    const __nv_bfloat16* Bbase = Bt + (size_t)nBase * K;
    const int nchunks = K / BK;

    // cp.async mapping: 16B per thread, 8 parts per 128B row
    const int ldRow  = tid >> 3;        // 0..31
    const int ldPart = tid & 7;         // 0..7
    const uint32_t ldOff = SWZ128((uint32_t)(ldRow * 128 + ldPart * 16));

    auto issue_loads = [&](int chunk, int s) {
        const char* ag = (const char*)(Abase + (size_t)chunk * BK) + (size_t)ldRow * K * 2 + ldPart * 16;
        const char* bg = (const char*)(Bbase + (size_t)chunk * BK) + (size_t)ldRow * K * 2 + ldPart * 16;
        const uint32_t sa = sbase + s * STAGE_BYTES + ldOff;
        const uint32_t sb = sa + A_BYTES;
        const size_t gstep = (size_t)32 * K * 2;      // 32 rows per iter
        #pragma unroll
        for (int i = 0; i < 4; i++)
            CP_ASYNC16(sa + i * (32 * 128), ag + i * gstep);
        #pragma unroll
        for (int i = 0; i < 4; i++)
            CP_ASYNC16(sb + i * (32 * 128), bg + i * gstep);
    };

    // ldmatrix lane->address components (swizzled smem, 128 B rows)
    // A x4: matrices (rows0-7,k0-7),(rows8-15,k0-7),(rows0-7,k8-15),(rows8-15,k8-15)
    const int aRowIn = (lane & 7) + ((lane >> 3) & 1) * 8;    // row within 16
    const int aK8    = (lane >> 4) * 8;                       // 0 or 8
    // B x4 over 2 n-tiles: matrices (n0-7,k0-7),(n0-7,k8-15),(n8-15,k0-7),(n8-15,k8-15)
    const int bMat   = lane >> 3;
    const int bNIn   = (bMat >> 1) * 8 + (lane & 7);          // n within 16
    const int bK8    = (bMat & 1) * 8;                        // 0 or 8

    float d[2][8][4];
    #pragma unroll
    for (int i = 0; i < 2; i++)
        #pragma unroll
        for (int j = 0; j < 8; j++)
            #pragma unroll
            for (int k = 0; k < 4; k++) d[i][j][k] = 0.f;

    // prologue: 2 stages in flight
    issue_loads(0, 0); CP_COMMIT();
    if (nchunks > 1) issue_loads(1, 1);
    CP_COMMIT();

    for (int c = 0; c < nchunks; ++c) {
        __syncthreads();                        // prior reads of stage (c+2)%3 done
        if (c + 2 < nchunks) issue_loads(c + 2, (c + 2) % STAGES);
        CP_COMMIT();
        CP_WAIT(2);                             // chunk c resident
        __syncthreads();

        const uint32_t sa = sbase + (c % STAGES) * STAGE_BYTES;
        const uint32_t sb = sa + A_BYTES;

        #pragma unroll
        for (int kk = 0; kk < 4; kk++) {
            uint32_t a[2][4];
            #pragma unroll
            for (int mt = 0; mt < 2; mt++) {
                int row  = warpM * 32 + mt * 16 + aRowIn;
                int kcol = kk * 16 + aK8;
                uint32_t addr = sa + SWZ128((uint32_t)(row * 128 + kcol * 2));
                LDMATRIX_X4(a[mt][0], a[mt][1], a[mt][2], a[mt][3], addr);
            }
            uint32_t b[4][4];                    // [n16 pair][4 regs]
            #pragma unroll
            for (int p = 0; p < 4; p++) {
                int n    = warpN * 64 + p * 16 + bNIn;
                int kcol = kk * 16 + bK8;
                uint32_t addr = sb + SWZ128((uint32_t)(n * 128 + kcol * 2));
                LDMATRIX_X4(b[p][0], b[p][1], b[p][2], b[p][3], addr);
            }
            #pragma unroll
            for (int mt = 0; mt < 2; mt++)
                #pragma unroll
                for (int p = 0; p < 4; p++) {
                    MMA_BF16(d[mt][2*p  ][0], d[mt][2*p  ][1], d[mt][2*p  ][2], d[mt][2*p  ][3],
                             a[mt][0], a[mt][1], a[mt][2], a[mt][3], b[p][0], b[p][1]);
                    MMA_BF16(d[mt][2*p+1][0], d[mt][2*p+1][1], d[mt][2*p+1][2], d[mt][2*p+1][3],
                             a[mt][0], a[mt][1], a[mt][2], a[mt][3], b[p][2], b[p][3]);
                }
        }
    }

    // epilogue: direct float2 stores + bias
    #pragma unroll
    for (int mt = 0; mt < 2; mt++) {
        const int row0 = mBase + warpM * 32 + mt * 16 + (lane >> 2);
        #pragma unroll
        for (int nt = 0; nt < 8; nt++) {
            const int col = nBase + warpN * 64 + nt * 8 + 2 * (lane & 3);
            const float2 bv = *reinterpret_cast<const float2*>(&bias[col]);
            float2 v0 = { d[mt][nt][0] + bv.x, d[mt][nt][1] + bv.y };
            float2 v1 = { d[mt][nt][2] + bv.x, d[mt][nt][3] + bv.y };
            *reinterpret_cast<float2*>(&C[(size_t)row0 * N + col])       = v0;
            *reinterpret_cast<float2*>(&C[(size_t)(row0 + 8) * N + col]) = v1;
        }
    }
}

// ---------------------------------------------------------------------------
// fp32 -> split bf16 (3-term: A segs [hi|hi|lo], B segs [hi|lo|hi])
// ---------------------------------------------------------------------------
__device__ __forceinline__ void bf16split(float v, __nv_bfloat16& hi, __nv_bfloat16& lo) {
    hi = __float2bfloat16_rn(v);
    lo = __float2bfloat16_rn(v - __bfloat162float(hi));
}

__global__ __launch_bounds__(256)
void split_x_kernel(const float* __restrict__ x, __nv_bfloat16* __restrict__ a1) {
    size_t i = (size_t)blockIdx.x * blockDim.x + threadIdx.x;
    if (i >= (size_t)MTOT * K1) return;
    size_t m = i / K1, k = i - m * K1;
    __nv_bfloat16 hi, lo; bf16split(x[i], hi, lo);
    __nv_bfloat16* r = a1 + m * K1S;
    r[k] = hi; r[K1 + k] = hi; r[2 * K1 + k] = lo;
}

__global__ __launch_bounds__(256)
void split_wT_kernel(const float* __restrict__ w, __nv_bfloat16* __restrict__ bt, int K, int N) {
    size_t i = (size_t)blockIdx.x * blockDim.x + threadIdx.x;
    if (i >= (size_t)K * N) return;
    int k = (int)(i / N), n = (int)(i - (size_t)k * N);
    __nv_bfloat16 hi, lo; bf16split(w[i], hi, lo);
    __nv_bfloat16* r = bt + (size_t)n * 3 * K;
    r[k] = hi; r[K + k] = lo; r[2 * K + k] = hi;
}

// ---------------------------------------------------------------------------
// Fused conv(4)+silu+EMA scan+gate; writes y directly in split-bf16 A2 layout.
// alpha^256 ~ 2e-12 -> chunks independent after 256-step warm-up.
// ---------------------------------------------------------------------------
__global__ __launch_bounds__(128)
void conv_scan_kernel(const float* __restrict__ xz,
                      const float* __restrict__ cw,
                      const float* __restrict__ cb,
                      const float* __restrict__ Dp,
                      __nv_bfloat16* __restrict__ a2)
{
    const int c  = blockIdx.x * 128 + threadIdx.x;
    const int t0 = blockIdx.y * LCHUNK;
    const int b  = blockIdx.z;
    const int ts = (t0 >= WARM) ? (t0 - WARM) : 0;

    const float w0 = cw[c * D_CONV + 0];
    const float w1 = cw[c * D_CONV + 1];
    const float w2 = cw[c * D_CONV + 2];
    const float w3 = cw[c * D_CONV + 3];
    const float cbias = cb[c];
    const float dpar  = Dp[c];
    const float AL = 0.9f, OMA = 0.1f;

    const float* base = xz + (size_t)b * SEQ * N1;

    float x0 = 0.f, x1 = 0.f, x2 = 0.f;
    #pragma unroll
    for (int dt = 3; dt >= 1; --dt) {
        int t = ts - dt;
        float v = (t >= 0) ? base[(size_t)t * N1 + c] : 0.f;
        x0 = x1; x1 = x2; x2 = v;
    }

    float h = 0.f;
    const int tend = t0 + LCHUNK;

    #pragma unroll 4
    for (int t = ts; t < tend; ++t) {
        float xt = base[(size_t)t * N1 + c];
        float conv = fmaf(w3, xt, fmaf(w2, x2, fmaf(w1, x1, fmaf(w0, x0, cbias))));
        x0 = x1; x1 = x2; x2 = xt;
        float xc = conv / (1.0f + __expf(-conv));
        h = fmaf(AL, h, OMA * xc);
        if (t >= t0) {
            float zv = base[(size_t)t * N1 + D_INNER + c];
            float sz = zv / (1.0f + __expf(-zv));
            float v = fmaf(xc, dpar, h) * sz;
            __nv_bfloat16 hi, lo; bf16split(v, hi, lo);
            __nv_bfloat16* r = a2 + ((size_t)b * SEQ + t) * K2S;
            r[c] = hi; r[D_INNER + c] = hi; r[2 * D_INNER + c] = lo;
        }
    }
}

// ---------------------------------------------------------------------------
extern "C" void kernel_launch(void* const* d_in, const int* in_sizes, int n_in,
                              void* d_out, int out_size)
{
    const float* x      = (const float*)d_in[0];
    const float* in_w   = (const float*)d_in[1];
    const float* in_b   = (const float*)d_in[2];
    const float* conv_w = (const float*)d_in[3];
    const float* conv_b = (const float*)d_in[4];
    const float* Dp     = (const float*)d_in[9];
    const float* out_w  = (const float*)d_in[10];
    const float* out_b  = (const float*)d_in[11];
    float* out = (float*)d_out;

    __nv_bfloat16 *a1, *b1, *a2, *b2; float* xz;
    cudaGetSymbolAddress((void**)&a1, g_a1);
    cudaGetSymbolAddress((void**)&b1, g_b1);
    cudaGetSymbolAddress((void**)&xz, g_xz);
    cudaGetSymbolAddress((void**)&a2, g_a2);
    cudaGetSymbolAddress((void**)&b2, g_b2);

    cudaFuncSetAttribute(gemm_bf16_mma, cudaFuncAttributeMaxDynamicSharedMemorySize, SMEM_TOTAL);

    // conversions
    {
        size_t n = (size_t)MTOT * K1;
        split_x_kernel<<<(unsigned)((n + 255) / 256), 256>>>(x, a1);
        size_t nw1 = (size_t)K1 * N1;
        split_wT_kernel<<<(unsigned)((nw1 + 255) / 256), 256>>>(in_w, b1, K1, N1);
        size_t nw2 = (size_t)K2 * N2;
        split_wT_kernel<<<(unsigned)((nw2 + 255) / 256), 256>>>(out_w, b2, K2, N2);
    }

    // GEMM1: xz = x @ in_w + in_b     [16384 x 3072], K'=2304
    dim3 g1(N1 / BN, MTOT / BM);
    gemm_bf16_mma<<<g1, NTHREADS, SMEM_TOTAL>>>(a1, b1, in_b, xz, MTOT, N1, K1S);

    // fused conv/silu/scan/gate -> a2 (split bf16)
    dim3 g2(D_INNER / 128, SEQ / LCHUNK, BATCH);
    conv_scan_kernel<<<g2, 128>>>(xz, conv_w, conv_b, Dp, a2);

    // GEMM2: out = y @ out_w + out_b  [16384 x 768], K'=4608
    dim3 g3(N2 / BN, MTOT / BM);
    gemm_bf16_mma<<<g3, NTHREADS, SMEM_TOTAL>>>(a2, b2, out_b, out, MTOT, N2, K2S);
}

// round 4
// speedup vs baseline: 3.0460x; 1.3738x over previous
#include <cuda_runtime.h>
#include <cuda_fp16.h>
#include <cstdint>

#define D_MODEL 768
#define D_CONV  4
#define D_INNER 1536
#define BATCH   2
#define SEQ     8192
#define MTOT    (BATCH*SEQ)     // 16384

#define K1  D_MODEL             // 768
#define N1  (2*D_INNER)         // 3072
#define K1S (2*K1)              // 1536
#define K2  D_INNER             // 1536
#define N2  D_MODEL             // 768
#define K2S (2*K2)              // 3072

#define BM 128
#define BN 128
#define BK 64                   // fp16 per chunk: 128 B/row = SW128 atom
#define STAGES 3
#define NTHREADS 256

#define LCHUNK 256
#define WARM   128

// ---------------- scratch (static device globals; no allocation) -----------
__device__ __half g_a1[(size_t)MTOT * K1S];   // x split [hi|lo]      (50 MB)
__device__ __half g_b1[(size_t)N1  * K1S];    // in_w^T  [hi|hi]      (9.4 MB)
__device__ float  g_xz[(size_t)MTOT * N1];    // GEMM1 out           (201 MB)
__device__ __half g_a2[(size_t)MTOT * K2S];   // y split [hi|lo]     (100 MB)
__device__ __half g_b2[(size_t)N2  * K2S];    // out_w^T [hi|hi]     (4.7 MB)

// ---------------- PTX helpers ----------------------------------------------
__device__ __forceinline__ uint32_t smem_u32(const void* p) {
    uint32_t a;
    asm("{ .reg .u64 t; cvta.to.shared.u64 t, %1; cvt.u32.u64 %0, t; }" : "=r"(a) : "l"(p));
    return a;
}
#define SWZ128(off) ((off) ^ (((off) >> 3) & 0x70))

#define CP_ASYNC16(s, g) \
    asm volatile("cp.async.cg.shared.global [%0], [%1], 16;\n" :: "r"(s), "l"(g) : "memory")
#define CP_COMMIT() asm volatile("cp.async.commit_group;\n" ::: "memory")
#define CP_WAIT(n)  asm volatile("cp.async.wait_group %0;\n" :: "n"(n) : "memory")

#define LDMATRIX_X4(r0, r1, r2, r3, addr) \
    asm volatile("ldmatrix.sync.aligned.m8n8.x4.shared.b16 {%0,%1,%2,%3}, [%4];" \
        : "=r"(r0), "=r"(r1), "=r"(r2), "=r"(r3) : "r"(addr))

#define MMA_F16(d0,d1,d2,d3, a0,a1,a2,a3, b0,b1) \
    asm volatile("mma.sync.aligned.m16n8k16.row.col.f32.f16.f16.f32 " \
        "{%0,%1,%2,%3}, {%4,%5,%6,%7}, {%8,%9}, {%0,%1,%2,%3};" \
        : "+f"(d0), "+f"(d1), "+f"(d2), "+f"(d3) \
        : "r"(a0), "r"(a1), "r"(a2), "r"(a3), "r"(b0), "r"(b1))

// SMEM per stage: A 128x64 fp16 (16 KB) + B 128x64 fp16 (16 KB)
#define A_BYTES (BM * 128)
#define B_BYTES (BN * 128)
#define STAGE_BYTES (A_BYTES + B_BYTES)     // 32768
#define SMEM_TOTAL (STAGES * STAGE_BYTES)   // 98304

// ---------------------------------------------------------------------------
// mma.sync fp16 GEMM: C[M,N] fp32 = A[M,K] @ Bt[N,K]^T + bias
// A, Bt K-major fp16. 128x128x64 tile, 3-stage cp.async, single barrier/chunk.
// ---------------------------------------------------------------------------
__global__ __launch_bounds__(NTHREADS, 2)
void gemm_f16_mma(const __half* __restrict__ A,
                  const __half* __restrict__ Bt,
                  const float* __restrict__ bias,
                  float* __restrict__ C,
                  int M, int N, int K)
{
    extern __shared__ char smem[];
    const uint32_t sbase = smem_u32(smem);
    const int tid  = threadIdx.x;
    const int wid  = tid >> 5;
    const int lane = tid & 31;
    const int warpM = wid & 3;          // 0..3  -> 32-row slice
    const int warpN = wid >> 2;         // 0..1  -> 64-col slice

    const int mBase = blockIdx.y * BM;
    const int nBase = blockIdx.x * BN;

    const __half* Abase = A  + (size_t)mBase * K;
    const __half* Bbase = Bt + (size_t)nBase * K;
    const int nchunks = K / BK;

    // cp.async mapping: 16B per thread, 8 parts per 128B row
    const int ldRow  = tid >> 3;        // 0..31
    const int ldPart = tid & 7;         // 0..7
    const uint32_t ldOff = SWZ128((uint32_t)(ldRow * 128 + ldPart * 16));

    auto issue_loads = [&](int chunk, int s) {
        const char* ag = (const char*)(Abase + (size_t)chunk * BK) + (size_t)ldRow * K * 2 + ldPart * 16;
        const char* bg = (const char*)(Bbase + (size_t)chunk * BK) + (size_t)ldRow * K * 2 + ldPart * 16;
        const uint32_t sa = sbase + s * STAGE_BYTES + ldOff;
        const uint32_t sb = sa + A_BYTES;
        const size_t gstep = (size_t)32 * K * 2;      // 32 rows per iter
        #pragma unroll
        for (int i = 0; i < 4; i++)
            CP_ASYNC16(sa + i * (32 * 128), ag + i * gstep);
        #pragma unroll
        for (int i = 0; i < 4; i++)
            CP_ASYNC16(sb + i * (32 * 128), bg + i * gstep);
    };

    // ldmatrix lane->address components (swizzled smem, 128 B rows)
    const int aRowIn = (lane & 7) + ((lane >> 3) & 1) * 8;    // row within 16
    const int aK8    = (lane >> 4) * 8;                       // 0 or 8
    const int bMat   = lane >> 3;
    const int bNIn   = (bMat >> 1) * 8 + (lane & 7);          // n within 16
    const int bK8    = (bMat & 1) * 8;                        // 0 or 8

    float d[2][8][4];
    #pragma unroll
    for (int i = 0; i < 2; i++)
        #pragma unroll
        for (int j = 0; j < 8; j++)
            #pragma unroll
            for (int k = 0; k < 4; k++) d[i][j][k] = 0.f;

    // prologue: 2 stages in flight (nchunks >= 24 always)
    issue_loads(0, 0); CP_COMMIT();
    issue_loads(1, 1); CP_COMMIT();

    for (int c = 0; c < nchunks; ++c) {
        CP_WAIT(1);                     // group c complete (<=1 group pending)
        __syncthreads();                // all warps see stage c; stage c-1 free
        if (c + 2 < nchunks) issue_loads(c + 2, (c + 2) % STAGES);
        CP_COMMIT();                    // unconditional: keeps group count uniform

        const uint32_t sa = sbase + (c % STAGES) * STAGE_BYTES;
        const uint32_t sb = sa + A_BYTES;

        #pragma unroll
        for (int kk = 0; kk < 4; kk++) {
            uint32_t a[2][4];
            #pragma unroll
            for (int mt = 0; mt < 2; mt++) {
                int row  = warpM * 32 + mt * 16 + aRowIn;
                int kcol = kk * 16 + aK8;
                uint32_t addr = sa + SWZ128((uint32_t)(row * 128 + kcol * 2));
                LDMATRIX_X4(a[mt][0], a[mt][1], a[mt][2], a[mt][3], addr);
            }
            uint32_t b[4][4];
            #pragma unroll
            for (int p = 0; p < 4; p++) {
                int n    = warpN * 64 + p * 16 + bNIn;
                int kcol = kk * 16 + bK8;
                uint32_t addr = sb + SWZ128((uint32_t)(n * 128 + kcol * 2));
                LDMATRIX_X4(b[p][0], b[p][1], b[p][2], b[p][3], addr);
            }
            #pragma unroll
            for (int mt = 0; mt < 2; mt++)
                #pragma unroll
                for (int p = 0; p < 4; p++) {
                    MMA_F16(d[mt][2*p  ][0], d[mt][2*p  ][1], d[mt][2*p  ][2], d[mt][2*p  ][3],
                            a[mt][0], a[mt][1], a[mt][2], a[mt][3], b[p][0], b[p][1]);
                    MMA_F16(d[mt][2*p+1][0], d[mt][2*p+1][1], d[mt][2*p+1][2], d[mt][2*p+1][3],
                            a[mt][0], a[mt][1], a[mt][2], a[mt][3], b[p][2], b[p][3]);
                }
        }
    }

    // epilogue: direct float2 stores + bias
    #pragma unroll
    for (int mt = 0; mt < 2; mt++) {
        const int row0 = mBase + warpM * 32 + mt * 16 + (lane >> 2);
        #pragma unroll
        for (int nt = 0; nt < 8; nt++) {
            const int col = nBase + warpN * 64 + nt * 8 + 2 * (lane & 3);
            const float2 bv = *reinterpret_cast<const float2*>(&bias[col]);
            float2 v0 = { d[mt][nt][0] + bv.x, d[mt][nt][1] + bv.y };
            float2 v1 = { d[mt][nt][2] + bv.x, d[mt][nt][3] + bv.y };
            *reinterpret_cast<float2*>(&C[(size_t)row0 * N + col])       = v0;
            *reinterpret_cast<float2*>(&C[(size_t)(row0 + 8) * N + col]) = v1;
        }
    }
}

// ---------------------------------------------------------------------------
// fp32 -> 2-term fp16 split: A segs [hi|lo], B segs [hi|hi]
// a_hi*b_hi + a_lo*b_hi = a*b_hi; dropped a*b_lo ~ 2^-12 rms relative.
// ---------------------------------------------------------------------------
__device__ __forceinline__ void f16split(float v, __half& hi, __half& lo) {
    hi = __float2half_rn(v);
    lo = __float2half_rn(v - __half2float(hi));
}

__global__ __launch_bounds__(256)
void split_x_kernel(const float* __restrict__ x, __half* __restrict__ a1) {
    size_t i = (size_t)blockIdx.x * blockDim.x + threadIdx.x;
    if (i >= (size_t)MTOT * K1) return;
    size_t m = i / K1, k = i - m * K1;
    __half hi, lo; f16split(x[i], hi, lo);
    __half* r = a1 + m * K1S;
    r[k] = hi; r[K1 + k] = lo;
}

__global__ __launch_bounds__(256)
void split_wT_kernel(const float* __restrict__ w, __half* __restrict__ bt, int K, int N) {
    size_t i = (size_t)blockIdx.x * blockDim.x + threadIdx.x;
    if (i >= (size_t)K * N) return;
    int k = (int)(i / N), n = (int)(i - (size_t)k * N);
    __half hi = __float2half_rn(w[i]);
    __half* r = bt + (size_t)n * 2 * K;
    r[k] = hi; r[K + k] = hi;
}

// ---------------------------------------------------------------------------
// Fused conv(4)+silu+EMA scan+gate; writes y directly in split-fp16 A2 layout.
// alpha^128 ~ 1.4e-6 -> chunks independent after 128-step warm-up.
// ---------------------------------------------------------------------------
__global__ __launch_bounds__(128)
void conv_scan_kernel(const float* __restrict__ xz,
                      const float* __restrict__ cw,
                      const float* __restrict__ cb,
                      const float* __restrict__ Dp,
                      __half* __restrict__ a2)
{
    const int c  = blockIdx.x * 128 + threadIdx.x;
    const int t0 = blockIdx.y * LCHUNK;
    const int b  = blockIdx.z;
    const int ts = (t0 >= WARM) ? (t0 - WARM) : 0;

    const float w0 = cw[c * D_CONV + 0];
    const float w1 = cw[c * D_CONV + 1];
    const float w2 = cw[c * D_CONV + 2];
    const float w3 = cw[c * D_CONV + 3];
    const float cbias = cb[c];
    const float dpar  = Dp[c];
    const float AL = 0.9f, OMA = 0.1f;

    const float* base = xz + (size_t)b * SEQ * N1;

    float x0 = 0.f, x1 = 0.f, x2 = 0.f;
    #pragma unroll
    for (int dt = 3; dt >= 1; --dt) {
        int t = ts - dt;
        float v = (t >= 0) ? base[(size_t)t * N1 + c] : 0.f;
        x0 = x1; x1 = x2; x2 = v;
    }

    float h = 0.f;
    const int tend = t0 + LCHUNK;

    #pragma unroll 4
    for (int t = ts; t < tend; ++t) {
        float xt = base[(size_t)t * N1 + c];
        float conv = fmaf(w3, xt, fmaf(w2, x2, fmaf(w1, x1, fmaf(w0, x0, cbias))));
        x0 = x1; x1 = x2; x2 = xt;
        float xc = conv / (1.0f + __expf(-conv));
        h = fmaf(AL, h, OMA * xc);
        if (t >= t0) {
            float zv = base[(size_t)t * N1 + D_INNER + c];
            float sz = zv / (1.0f + __expf(-zv));
            float v = fmaf(xc, dpar, h) * sz;
            __half hi, lo; f16split(v, hi, lo);
            __half* r = a2 + ((size_t)b * SEQ + t) * K2S;
            r[c] = hi; r[D_INNER + c] = lo;
        }
    }
}

// ---------------------------------------------------------------------------
extern "C" void kernel_launch(void* const* d_in, const int* in_sizes, int n_in,
                              void* d_out, int out_size)
{
    const float* x      = (const float*)d_in[0];
    const float* in_w   = (const float*)d_in[1];
    const float* in_b   = (const float*)d_in[2];
    const float* conv_w = (const float*)d_in[3];
    const float* conv_b = (const float*)d_in[4];
    const float* Dp     = (const float*)d_in[9];
    const float* out_w  = (const float*)d_in[10];
    const float* out_b  = (const float*)d_in[11];
    float* out = (float*)d_out;

    __half *a1, *b1, *a2, *b2; float* xz;
    cudaGetSymbolAddress((void**)&a1, g_a1);
    cudaGetSymbolAddress((void**)&b1, g_b1);
    cudaGetSymbolAddress((void**)&xz, g_xz);
    cudaGetSymbolAddress((void**)&a2, g_a2);
    cudaGetSymbolAddress((void**)&b2, g_b2);

    cudaFuncSetAttribute(gemm_f16_mma, cudaFuncAttributeMaxDynamicSharedMemorySize, SMEM_TOTAL);

    // conversions
    {
        size_t n = (size_t)MTOT * K1;
        split_x_kernel<<<(unsigned)((n + 255) / 256), 256>>>(x, a1);
        size_t nw1 = (size_t)K1 * N1;
        split_wT_kernel<<<(unsigned)((nw1 + 255) / 256), 256>>>(in_w, b1, K1, N1);
        size_t nw2 = (size_t)K2 * N2;
        split_wT_kernel<<<(unsigned)((nw2 + 255) / 256), 256>>>(out_w, b2, K2, N2);
    }

    // GEMM1: xz = x @ in_w + in_b     [16384 x 3072], K'=1536
    dim3 g1(N1 / BN, MTOT / BM);
    gemm_f16_mma<<<g1, NTHREADS, SMEM_TOTAL>>>(a1, b1, in_b, xz, MTOT, N1, K1S);

    // fused conv/silu/scan/gate -> a2 (split fp16)
    dim3 g2(D_INNER / 128, SEQ / LCHUNK, BATCH);
    conv_scan_kernel<<<g2, 128>>>(xz, conv_w, conv_b, Dp, a2);

    // GEMM2: out = y @ out_w + out_b  [16384 x 768], K'=3072
    dim3 g3(N2 / BN, MTOT / BM);
    gemm_f16_mma<<<g3, NTHREADS, SMEM_TOTAL>>>(a2, b2, out_b, out, MTOT, N2, K2S);
}

// round 5
// speedup vs baseline: 4.4220x; 1.4517x over previous
#include <cuda_runtime.h>
#include <cuda_fp16.h>
#include <cstdint>

#define D_MODEL 768
#define D_CONV  4
#define D_INNER 1536
#define BATCH   2
#define SEQ     8192
#define MTOT    (BATCH*SEQ)     // 16384

#define K1  D_MODEL             // 768
#define N1  (2*D_INNER)         // 3072
#define K2  D_INNER             // 1536
#define N2  D_MODEL             // 768

#define BM 128
#define BN 128
#define BK 64                   // fp16 per chunk: 128 B/row = SW128 atom
#define STAGES 3
#define NTHREADS 256

#define LCHUNK 256
#define WARM   128

// ---------------- scratch (static device globals; no allocation) -----------
__device__ __half g_a1[(size_t)MTOT * K1];    // fp16(x)        (25 MB)
__device__ __half g_b1[(size_t)N1  * K1];     // fp16(in_w^T)   (4.7 MB)
__device__ float  g_xz[(size_t)MTOT * N1];    // GEMM1 out      (201 MB)
__device__ __half g_a2[(size_t)MTOT * K2];    // fp16(y)        (50 MB)
__device__ __half g_b2[(size_t)N2  * K2];     // fp16(out_w^T)  (2.4 MB)

// ---------------- PTX helpers ----------------------------------------------
__device__ __forceinline__ uint32_t smem_u32(const void* p) {
    uint32_t a;
    asm("{ .reg .u64 t; cvta.to.shared.u64 t, %1; cvt.u32.u64 %0, t; }" : "=r"(a) : "l"(p));
    return a;
}
#define SWZ128(off) ((off) ^ (((off) >> 3) & 0x70))

#define CP_ASYNC16(s, g) \
    asm volatile("cp.async.cg.shared.global [%0], [%1], 16;\n" :: "r"(s), "l"(g) : "memory")
#define CP_COMMIT() asm volatile("cp.async.commit_group;\n" ::: "memory")
#define CP_WAIT(n)  asm volatile("cp.async.wait_group %0;\n" :: "n"(n) : "memory")

#define LDMATRIX_X4(r0, r1, r2, r3, addr) \
    asm volatile("ldmatrix.sync.aligned.m8n8.x4.shared.b16 {%0,%1,%2,%3}, [%4];" \
        : "=r"(r0), "=r"(r1), "=r"(r2), "=r"(r3) : "r"(addr))

#define MMA_F16(d0,d1,d2,d3, a0,a1,a2,a3, b0,b1) \
    asm volatile("mma.sync.aligned.m16n8k16.row.col.f32.f16.f16.f32 " \
        "{%0,%1,%2,%3}, {%4,%5,%6,%7}, {%8,%9}, {%0,%1,%2,%3};" \
        : "+f"(d0), "+f"(d1), "+f"(d2), "+f"(d3) \
        : "r"(a0), "r"(a1), "r"(a2), "r"(a3), "r"(b0), "r"(b1))

// SMEM per stage: A 128x64 fp16 (16 KB) + B 128x64 fp16 (16 KB)
#define A_BYTES (BM * 128)
#define B_BYTES (BN * 128)
#define STAGE_BYTES (A_BYTES + B_BYTES)     // 32768
#define SMEM_TOTAL (STAGES * STAGE_BYTES)   // 98304

// ---------------------------------------------------------------------------
// mma.sync fp16 GEMM: C[M,N] fp32 = A[M,K] @ Bt[N,K]^T + bias
// A, Bt K-major fp16. 128x128x64 tile, 3-stage cp.async, single barrier/chunk.
// ---------------------------------------------------------------------------
__global__ __launch_bounds__(NTHREADS, 2)
void gemm_f16_mma(const __half* __restrict__ A,
                  const __half* __restrict__ Bt,
                  const float* __restrict__ bias,
                  float* __restrict__ C,
                  int M, int N, int K)
{
    extern __shared__ char smem[];
    const uint32_t sbase = smem_u32(smem);
    const int tid  = threadIdx.x;
    const int wid  = tid >> 5;
    const int lane = tid & 31;
    const int warpM = wid & 3;          // 0..3  -> 32-row slice
    const int warpN = wid >> 2;         // 0..1  -> 64-col slice

    const int mBase = blockIdx.y * BM;
    const int nBase = blockIdx.x * BN;

    const __half* Abase = A  + (size_t)mBase * K;
    const __half* Bbase = Bt + (size_t)nBase * K;
    const int nchunks = K / BK;

    // cp.async mapping: 16B per thread, 8 parts per 128B row
    const int ldRow  = tid >> 3;        // 0..31
    const int ldPart = tid & 7;         // 0..7
    const uint32_t ldOff = SWZ128((uint32_t)(ldRow * 128 + ldPart * 16));

    auto issue_loads = [&](int chunk, int s) {
        const char* ag = (const char*)(Abase + (size_t)chunk * BK) + (size_t)ldRow * K * 2 + ldPart * 16;
        const char* bg = (const char*)(Bbase + (size_t)chunk * BK) + (size_t)ldRow * K * 2 + ldPart * 16;
        const uint32_t sa = sbase + s * STAGE_BYTES + ldOff;
        const uint32_t sb = sa + A_BYTES;
        const size_t gstep = (size_t)32 * K * 2;      // 32 rows per iter
        #pragma unroll
        for (int i = 0; i < 4; i++)
            CP_ASYNC16(sa + i * (32 * 128), ag + i * gstep);
        #pragma unroll
        for (int i = 0; i < 4; i++)
            CP_ASYNC16(sb + i * (32 * 128), bg + i * gstep);
    };

    // ldmatrix lane->address components (swizzled smem, 128 B rows)
    const int aRowIn = (lane & 7) + ((lane >> 3) & 1) * 8;    // row within 16
    const int aK8    = (lane >> 4) * 8;                       // 0 or 8
    const int bMat   = lane >> 3;
    const int bNIn   = (bMat >> 1) * 8 + (lane & 7);          // n within 16
    const int bK8    = (bMat & 1) * 8;                        // 0 or 8

    float d[2][8][4];
    #pragma unroll
    for (int i = 0; i < 2; i++)
        #pragma unroll
        for (int j = 0; j < 8; j++)
            #pragma unroll
            for (int k = 0; k < 4; k++) d[i][j][k] = 0.f;

    // prologue: 2 stages in flight (nchunks >= 12 always)
    issue_loads(0, 0); CP_COMMIT();
    issue_loads(1, 1); CP_COMMIT();

    for (int c = 0; c < nchunks; ++c) {
        CP_WAIT(1);                     // group c complete (<=1 group pending)
        __syncthreads();                // all warps see stage c; stage c-1 free
        if (c + 2 < nchunks) issue_loads(c + 2, (c + 2) % STAGES);
        CP_COMMIT();                    // unconditional: keeps group count uniform

        const uint32_t sa = sbase + (c % STAGES) * STAGE_BYTES;
        const uint32_t sb = sa + A_BYTES;

        #pragma unroll
        for (int kk = 0; kk < 4; kk++) {
            uint32_t a[2][4];
            #pragma unroll
            for (int mt = 0; mt < 2; mt++) {
                int row  = warpM * 32 + mt * 16 + aRowIn;
                int kcol = kk * 16 + aK8;
                uint32_t addr = sa + SWZ128((uint32_t)(row * 128 + kcol * 2));
                LDMATRIX_X4(a[mt][0], a[mt][1], a[mt][2], a[mt][3], addr);
            }
            uint32_t b[4][4];
            #pragma unroll
            for (int p = 0; p < 4; p++) {
                int n    = warpN * 64 + p * 16 + bNIn;
                int kcol = kk * 16 + bK8;
                uint32_t addr = sb + SWZ128((uint32_t)(n * 128 + kcol * 2));
                LDMATRIX_X4(b[p][0], b[p][1], b[p][2], b[p][3], addr);
            }
            #pragma unroll
            for (int mt = 0; mt < 2; mt++)
                #pragma unroll
                for (int p = 0; p < 4; p++) {
                    MMA_F16(d[mt][2*p  ][0], d[mt][2*p  ][1], d[mt][2*p  ][2], d[mt][2*p  ][3],
                            a[mt][0], a[mt][1], a[mt][2], a[mt][3], b[p][0], b[p][1]);
                    MMA_F16(d[mt][2*p+1][0], d[mt][2*p+1][1], d[mt][2*p+1][2], d[mt][2*p+1][3],
                            a[mt][0], a[mt][1], a[mt][2], a[mt][3], b[p][2], b[p][3]);
                }
        }
    }

    // epilogue: direct float2 stores + bias
    #pragma unroll
    for (int mt = 0; mt < 2; mt++) {
        const int row0 = mBase + warpM * 32 + mt * 16 + (lane >> 2);
        #pragma unroll
        for (int nt = 0; nt < 8; nt++) {
            const int col = nBase + warpN * 64 + nt * 8 + 2 * (lane & 3);
            const float2 bv = *reinterpret_cast<const float2*>(&bias[col]);
            float2 v0 = { d[mt][nt][0] + bv.x, d[mt][nt][1] + bv.y };
            float2 v1 = { d[mt][nt][2] + bv.x, d[mt][nt][3] + bv.y };
            *reinterpret_cast<float2*>(&C[(size_t)row0 * N + col])       = v0;
            *reinterpret_cast<float2*>(&C[(size_t)(row0 + 8) * N + col]) = v1;
        }
    }
}

// ---------------------------------------------------------------------------
// fp32 -> fp16 conversion kernels
// ---------------------------------------------------------------------------
__global__ __launch_bounds__(256)
void cvt_x_kernel(const float* __restrict__ x, __half* __restrict__ a1) {
    size_t i = ((size_t)blockIdx.x * blockDim.x + threadIdx.x) * 4;
    if (i >= (size_t)MTOT * K1) return;
    float4 v = *reinterpret_cast<const float4*>(&x[i]);
    __half2* o = reinterpret_cast<__half2*>(&a1[i]);
    o[0] = __floats2half2_rn(v.x, v.y);
    o[1] = __floats2half2_rn(v.z, v.w);
}

// w [K,N] -> bt [N,K] fp16 transpose
__global__ __launch_bounds__(256)
void cvt_wT_kernel(const float* __restrict__ w, __half* __restrict__ bt, int K, int N) {
    size_t i = (size_t)blockIdx.x * blockDim.x + threadIdx.x;
    if (i >= (size_t)K * N) return;
    int k = (int)(i / N), n = (int)(i - (size_t)k * N);
    bt[(size_t)n * K + k] = __float2half_rn(w[i]);
}

// ---------------------------------------------------------------------------
// Fused conv(4)+silu+EMA scan+gate; writes y as fp16 A2 for GEMM2.
// alpha^128 ~ 1.4e-6 -> chunks independent after 128-step warm-up.
// ---------------------------------------------------------------------------
__global__ __launch_bounds__(128)
void conv_scan_kernel(const float* __restrict__ xz,
                      const float* __restrict__ cw,
                      const float* __restrict__ cb,
                      const float* __restrict__ Dp,
                      __half* __restrict__ a2)
{
    const int c  = blockIdx.x * 128 + threadIdx.x;
    const int t0 = blockIdx.y * LCHUNK;
    const int b  = blockIdx.z;
    const int ts = (t0 >= WARM) ? (t0 - WARM) : 0;

    const float w0 = cw[c * D_CONV + 0];
    const float w1 = cw[c * D_CONV + 1];
    const float w2 = cw[c * D_CONV + 2];
    const float w3 = cw[c * D_CONV + 3];
    const float cbias = cb[c];
    const float dpar  = Dp[c];
    const float AL = 0.9f, OMA = 0.1f;

    const float* base = xz + (size_t)b * SEQ * N1;

    float x0 = 0.f, x1 = 0.f, x2 = 0.f;
    #pragma unroll
    for (int dt = 3; dt >= 1; --dt) {
        int t = ts - dt;
        float v = (t >= 0) ? base[(size_t)t * N1 + c] : 0.f;
        x0 = x1; x1 = x2; x2 = v;
    }

    float h = 0.f;
    const int tend = t0 + LCHUNK;

    #pragma unroll 4
    for (int t = ts; t < tend; ++t) {
        float xt = base[(size_t)t * N1 + c];
        float conv = fmaf(w3, xt, fmaf(w2, x2, fmaf(w1, x1, fmaf(w0, x0, cbias))));
        x0 = x1; x1 = x2; x2 = xt;
        float xc = conv / (1.0f + __expf(-conv));
        h = fmaf(AL, h, OMA * xc);
        if (t >= t0) {
            float zv = base[(size_t)t * N1 + D_INNER + c];
            float sz = zv / (1.0f + __expf(-zv));
            float v = fmaf(xc, dpar, h) * sz;
            a2[((size_t)b * SEQ + t) * K2 + c] = __float2half_rn(v);
        }
    }
}

// ---------------------------------------------------------------------------
extern "C" void kernel_launch(void* const* d_in, const int* in_sizes, int n_in,
                              void* d_out, int out_size)
{
    const float* x      = (const float*)d_in[0];
    const float* in_w   = (const float*)d_in[1];
    const float* in_b   = (const float*)d_in[2];
    const float* conv_w = (const float*)d_in[3];
    const float* conv_b = (const float*)d_in[4];
    const float* Dp     = (const float*)d_in[9];
    const float* out_w  = (const float*)d_in[10];
    const float* out_b  = (const float*)d_in[11];
    float* out = (float*)d_out;

    __half *a1, *b1, *a2, *b2; float* xz;
    cudaGetSymbolAddress((void**)&a1, g_a1);
    cudaGetSymbolAddress((void**)&b1, g_b1);
    cudaGetSymbolAddress((void**)&xz, g_xz);
    cudaGetSymbolAddress((void**)&a2, g_a2);
    cudaGetSymbolAddress((void**)&b2, g_b2);

    cudaFuncSetAttribute(gemm_f16_mma, cudaFuncAttributeMaxDynamicSharedMemorySize, SMEM_TOTAL);

    // conversions
    {
        size_t n4 = (size_t)MTOT * K1 / 4;
        cvt_x_kernel<<<(unsigned)((n4 + 255) / 256), 256>>>(x, a1);
        size_t nw1 = (size_t)K1 * N1;
        cvt_wT_kernel<<<(unsigned)((nw1 + 255) / 256), 256>>>(in_w, b1, K1, N1);
        size_t nw2 = (size_t)K2 * N2;
        cvt_wT_kernel<<<(unsigned)((nw2 + 255) / 256), 256>>>(out_w, b2, K2, N2);
    }

    // GEMM1: xz = x @ in_w + in_b     [16384 x 3072], K=768
    dim3 g1(N1 / BN, MTOT / BM);
    gemm_f16_mma<<<g1, NTHREADS, SMEM_TOTAL>>>(a1, b1, in_b, xz, MTOT, N1, K1);

    // fused conv/silu/scan/gate -> a2 (fp16)
    dim3 g2(D_INNER / 128, SEQ / LCHUNK, BATCH);
    conv_scan_kernel<<<g2, 128>>>(xz, conv_w, conv_b, Dp, a2);

    // GEMM2: out = y @ out_w + out_b  [16384 x 768], K=1536
    dim3 g3(N2 / BN, MTOT / BM);
    gemm_f16_mma<<<g3, NTHREADS, SMEM_TOTAL>>>(a2, b2, out_b, out, MTOT, N2, K2);
}